// round 4
// baseline (speedup 1.0000x reference)
#include <cuda_runtime.h>

#define BB  2
#define LL  1024
#define DD  768
#define HH  12
#define DHD 64
#define BHN (BB*HH)

// ---- scratch (device globals: allowed; no runtime allocation) ----
__device__ float g_q [BHN*LL*DHD];
__device__ float g_k [BHN*LL*DHD];
__device__ float g_v [BHN*LL*DHD];
__device__ float g_qw[5*BHN*LL*DHD];
__device__ float g_s [(size_t)BHN*LL*LL];

// ============================================================
// tf32 helpers
// ============================================================
__device__ __forceinline__ unsigned f2tf(float x) {
    unsigned u; asm("cvt.rna.tf32.f32 %0, %1;" : "=r"(u) : "f"(x)); return u;
}

__device__ __forceinline__ void mma8(float* c, const uint4 a, const uint2 b) {
    asm volatile(
        "mma.sync.aligned.m16n8k8.row.col.f32.tf32.tf32.f32 "
        "{%0,%1,%2,%3}, {%4,%5,%6,%7}, {%8,%9}, {%0,%1,%2,%3};"
        : "+f"(c[0]), "+f"(c[1]), "+f"(c[2]), "+f"(c[3])
        : "r"(a.x), "r"(a.y), "r"(a.z), "r"(a.w), "r"(b.x), "r"(b.y));
}

// ---------- split LDG / STS staging ----------
// Row-major 128x64 tile load (rows m, 16 float4 per row). nvalid rows; rest zero.
template<int ITERS, int TPB>
__device__ __forceinline__ void ldgT(float4* v, const float* __restrict__ src,
                                     int ld, int tid, int nvalid) {
    #pragma unroll
    for (int it = 0; it < ITERS; it++) {
        int idx = tid + it*TPB;
        int m = idx >> 4, k4 = idx & 15;
        v[it] = (m < nvalid) ? *(const float4*)(src + (size_t)m*ld + k4*4)
                             : make_float4(0.f,0.f,0.f,0.f);
    }
}

// STS to A-fragment layout: Af[ks(8)][mt(8)][lane(32)][4] (8192 u32 = 32KB)
template<int ITERS, int TPB>
__device__ __forceinline__ void stsA_(unsigned* dst, const float4* v, int tid) {
    #pragma unroll
    for (int it = 0; it < ITERS; it++) {
        int idx = tid + it*TPB;
        int m = idx >> 4, k4 = idx & 15;
        int mt = m >> 4, r = m & 15;
        int rbit = (r >> 3) & 1;
        int laneb = (r & 7) << 2;
        float vv[4] = {v[it].x, v[it].y, v[it].z, v[it].w};
        #pragma unroll
        for (int c2 = 0; c2 < 4; c2++) {
            int k  = k4*4 + c2;
            int ks = k >> 3, cc = k & 3, hf = (k >> 2) & 1;
            dst[((ks*8 + mt)*32 + (laneb | cc))*4 + (rbit + hf*2)] = f2tf(vv[c2]);
        }
    }
}

// STS to B-fragment layout: Bf[ks(8)][nt(16)][lane(32)][2] (8192 u32 = 32KB)
template<int ITERS, int TPB>
__device__ __forceinline__ void stsB_(unsigned* dst, const float4* v, int tid) {
    #pragma unroll
    for (int it = 0; it < ITERS; it++) {
        int idx = tid + it*TPB;
        int n = idx >> 4, k4 = idx & 15;
        int nt = n >> 3;
        int laneb = (n & 7) << 2;
        float vv[4] = {v[it].x, v[it].y, v[it].z, v[it].w};
        #pragma unroll
        for (int c2 = 0; c2 < 4; c2++) {
            int k  = k4*4 + c2;
            int ks = k >> 3, cc = k & 3, hf = (k >> 2) & 1;
            dst[((ks*16 + nt)*32 + (laneb | cc))*2 + hf] = f2tf(vv[c2]);
        }
    }
}

// k-major 64 x N tile load (for W / ssan_w / v).
template<int ITERS, int TPB, int N>
__device__ __forceinline__ void ldgBT(float4* v, const float* __restrict__ src,
                                      int ldn, int tid) {
    constexpr int F4 = N / 4;
    #pragma unroll
    for (int it = 0; it < ITERS; it++) {
        int idx = tid + it*TPB;
        int k = idx / F4, nq = idx % F4;
        v[it] = *(const float4*)(src + (size_t)k*ldn + nq*4);
    }
}

template<int ITERS, int TPB, int N>
__device__ __forceinline__ void stsBT_(unsigned* dst, const float4* v, int tid) {
    constexpr int NT = N / 8;
    constexpr int F4 = N / 4;
    #pragma unroll
    for (int it = 0; it < ITERS; it++) {
        int idx = tid + it*TPB;
        int k = idx / F4, nq = idx % F4;
        int ks = k >> 3, cc = k & 3, hf = (k >> 2) & 1;
        float vv[4] = {v[it].x, v[it].y, v[it].z, v[it].w};
        #pragma unroll
        for (int c2 = 0; c2 < 4; c2++) {
            int n = nq*4 + c2;
            int nt = n >> 3, laneb = (n & 7) << 2;
            dst[((ks*NT + nt)*32 + (laneb | cc))*2 + hf] = f2tf(vv[c2]);
        }
    }
}

// 128x128x64 GEMM pass: warp tile 32x64 (warp grid 4m x 2n).
__device__ __forceinline__ void gemm64(const unsigned* __restrict__ Af,
                                       const unsigned* __restrict__ Bf,
                                       int wm, int wn, int lane, float bacc[2][8][4]) {
    #pragma unroll
    for (int ks = 0; ks < 8; ks++) {
        uint4 a0 = *(const uint4*)(Af + ((ks*8 + wm*2 + 0)*32 + lane)*4);
        uint4 a1 = *(const uint4*)(Af + ((ks*8 + wm*2 + 1)*32 + lane)*4);
        #pragma unroll
        for (int j = 0; j < 8; j++) {
            uint2 b = *(const uint2*)(Bf + ((ks*16 + wn*8 + j)*32 + lane)*2);
            mma8(bacc[0][j], a0, b);
            mma8(bacc[1][j], a1, b);
        }
    }
}

// 128x64x64 GEMM pass: 8 warps, warp wid owns 16-row group. acc[8][4].
__device__ __forceinline__ void gemm64n64(const unsigned* __restrict__ Af,
                                          const unsigned* __restrict__ Bf,
                                          int wid, int lane, float acc[8][4]) {
    #pragma unroll
    for (int ks = 0; ks < 8; ks++) {
        uint4 a = *(const uint4*)(Af + ((ks*8 + wid)*32 + lane)*4);
        #pragma unroll
        for (int j = 0; j < 8; j++) {
            uint2 b = *(const uint2*)(Bf + ((ks*8 + j)*32 + lane)*2);
            mma8(acc[j], a, b);
        }
    }
}

__device__ __forceinline__ void zeroacc(float a[2][8][4]) {
    #pragma unroll
    for (int i = 0; i < 2; i++)
        #pragma unroll
        for (int j = 0; j < 8; j++)
            #pragma unroll
            for (int c = 0; c < 4; c++) a[i][j][c] = 0.f;
}

__device__ __forceinline__ void writeQE(float* buf, const float bacc[2][8][4],
                                        int wm, int wn, int lane) {
    int r0 = wm*32 + (lane >> 2);
    int c0 = wn*64 + (lane & 3)*2;
    #pragma unroll
    for (int i = 0; i < 2; i++)
        #pragma unroll
        for (int j = 0; j < 8; j++) {
            int rr = r0 + i*16, cc = c0 + j*8;
            *(float2*)(buf + rr*132 + cc)      = make_float2(bacc[i][j][0], bacc[i][j][1]);
            *(float2*)(buf + (rr+8)*132 + cc)  = make_float2(bacc[i][j][2], bacc[i][j][3]);
        }
}

__device__ __forceinline__ void gatherDiag(const float* __restrict__ buf, float acc[2][8][4],
                                           int wm, int wn, int lane, int half, bool useCol) {
    int r0 = wm*32 + (lane >> 2);
    int c0 = wn*64 + (lane & 3)*2;
    int off = 127 - half*128;
    #pragma unroll
    for (int i = 0; i < 2; i++)
        #pragma unroll
        for (int j = 0; j < 8; j++) {
            int rr = r0 + i*16, cc = c0 + j*8;
            #pragma unroll
            for (int c2 = 0; c2 < 4; c2++) {
                int R = rr + (c2 >> 1)*8;
                int C = cc + (c2 & 1);
                int J = R - C + off;
                if ((unsigned)J < 128u) {
                    int rowi = useCol ? C : R;
                    acc[i][j][c2] += buf[rowi*132 + J];
                }
            }
        }
}

// ============================================================
// K1: QKV projection, tf32, 2-stage pipelined. smem 128KB.
// ============================================================
__global__ __launch_bounds__(256) void qkv_kernel(
    const float* __restrict__ hidden,
    const float* __restrict__ Wq, const float* __restrict__ bq,
    const float* __restrict__ Wk, const float* __restrict__ bk,
    const float* __restrict__ Wv, const float* __restrict__ bv)
{
    extern __shared__ unsigned smu[];
    unsigned* AF[2] = { smu,        smu + 16384 };
    unsigned* BF[2] = { smu + 8192, smu + 24576 };

    const int mat = blockIdx.z;
    const float* W    = (mat==0) ? Wq : (mat==1 ? Wk : Wv);
    const float* bias = (mat==0) ? bq : (mat==1 ? bk : bv);
    float* outp       = (mat==0) ? g_q : (mat==1 ? g_k : g_v);

    const int n0 = blockIdx.x * 128;
    const int m0 = blockIdx.y * 128;
    const int tid = threadIdx.x, lane = tid & 31, wid = tid >> 5;
    const int wm = wid & 3, wn = wid >> 2;

    float acc[2][8][4];
    zeroacc(acc);

    float4 vA[8], vB[8];
    ldgT<8,256>(vA, hidden + (size_t)m0*DD, DD, tid, 128);
    ldgBT<8,256,128>(vB, W + n0, DD, tid);
    stsA_<8,256>(AF[0], vA, tid);
    stsBT_<8,256,128>(BF[0], vB, tid);
    ldgT<8,256>(vA, hidden + (size_t)m0*DD + 64, DD, tid, 128);
    ldgBT<8,256,128>(vB, W + (size_t)64*DD + n0, DD, tid);
    __syncthreads();

    for (int c = 0; c < 12; c++) {
        int cur = c & 1;
        if (c < 11) {
            stsA_<8,256>(AF[1-cur], vA, tid);
            stsBT_<8,256,128>(BF[1-cur], vB, tid);
        }
        if (c < 10) {
            ldgT<8,256>(vA, hidden + (size_t)m0*DD + (c+2)*64, DD, tid, 128);
            ldgBT<8,256,128>(vB, W + (size_t)((c+2)*64)*DD + n0, DD, tid);
        }
        gemm64(AF[cur], BF[cur], wm, wn, lane, acc);
        __syncthreads();
    }

    const int r0 = wm*32 + (lane >> 2);
    const int c0 = wn*64 + (lane & 3)*2;
    #pragma unroll
    for (int i = 0; i < 2; i++)
        #pragma unroll
        for (int j = 0; j < 8; j++) {
            int cc = c0 + j*8;
            int cg = n0 + cc;
            int h = cg >> 6, dh = cg & 63;
            float2 bb = *(const float2*)(bias + cg);
            #pragma unroll
            for (int half = 0; half < 2; half++) {
                int rg = m0 + r0 + i*16 + half*8;
                int b = rg >> 10, l = rg & 1023;
                float2 v = make_float2(acc[i][j][half*2+0] + bb.x,
                                       acc[i][j][half*2+1] + bb.y);
                *(float2*)&outp[((b*HH + h)*LL + l)*DHD + dh] = v;
            }
        }
}

// ============================================================
// K1b: qw = q @ ssan_w[i][h]. Single chunk K=64. smem 48KB.
// ============================================================
__global__ __launch_bounds__(256) void qw_kernel(const float* __restrict__ ssw)
{
    extern __shared__ unsigned smu[];
    unsigned* Af = smu;
    unsigned* Bf = smu + 8192;

    const int i5 = blockIdx.z;
    const int bh = blockIdx.y;
    const int h  = bh % HH;
    const int m0 = blockIdx.x * 128;
    const int tid = threadIdx.x, lane = tid & 31, wid = tid >> 5;

    float4 vA[8], vB[4];
    ldgT<8,256>(vA, g_q + (size_t)(bh*LL + m0)*DHD, DHD, tid, 128);
    ldgBT<4,256,64>(vB, ssw + (size_t)(i5*HH + h)*DHD*DHD, DHD, tid);
    stsA_<8,256>(Af, vA, tid);
    stsBT_<4,256,64>(Bf, vB, tid);
    __syncthreads();

    float acc[8][4];
    #pragma unroll
    for (int j = 0; j < 8; j++)
        #pragma unroll
        for (int c = 0; c < 4; c++) acc[j][c] = 0.f;

    gemm64n64(Af, Bf, wid, lane, acc);

    float* ob = g_qw + ((size_t)(i5*BHN + bh)*LL + m0)*DHD;
    const int r0 = wid*16 + (lane >> 2);
    const int c0 = (lane & 3)*2;
    #pragma unroll
    for (int j = 0; j < 8; j++) {
        int cc = c0 + j*8;
        *(float2*)(ob + (size_t)r0*DHD + cc)     = make_float2(acc[j][0], acc[j][1]);
        *(float2*)(ob + (size_t)(r0+8)*DHD + cc) = make_float2(acc[j][2], acc[j][3]);
    }
}

// ============================================================
// K2: fused scores, pipelined. smem 231424B (1 CTA/SM).
// Buffers: Qf|Kb|Ka|E0|E1 (32KB each) + QEb 128*132 f32.
// qw stagings double-buffered through Ka/E0/E1 as they free up.
// ============================================================
#define SMEM_SCORES 231424

__global__ __launch_bounds__(256, 1) void scores_kernel(
    const float* __restrict__ mask,
    const float* __restrict__ structm,
    const float* __restrict__ dist,
    const float* __restrict__ abv)
{
    extern __shared__ unsigned smu[];
    unsigned* Qf = smu;
    unsigned* Kb = smu + 8192;
    unsigned* Ka = smu + 16384;
    unsigned* E0 = smu + 24576;
    unsigned* E1 = smu + 32768;
    float*   QEb = (float*)(smu + 40960);

    const int bh = blockIdx.x, kt = blockIdx.y, qt = blockIdx.z;
    const int b = bh / HH, h = bh % HH;
    const int m0 = qt*128, n0 = kt*128;
    const int tid = threadIdx.x, lane = tid & 31, wid = tid >> 5;
    const int wm = wid & 3, wn = wid >> 2;

    const int base = (qt - kt)*128 + 896;
    int nv1 = 1919 - base; if (nv1 > 128) nv1 = 128;

    // ---- prologue: stage q, k(x2), E0, E1 ----
    float4 va[8], vb[8];
    ldgT<8,256>(va, g_q + (size_t)(bh*LL + m0)*DHD, DHD, tid, 128);
    ldgT<8,256>(vb, g_k + (size_t)(bh*LL + n0)*DHD, DHD, tid, 128);
    stsA_<8,256>(Qf, va, tid);
    ldgT<8,256>(va, dist + (size_t)base*DHD, DHD, tid, 128);
    stsB_<8,256>(Kb, vb, tid);
    stsA_<8,256>(Ka, vb, tid);
    ldgT<8,256>(vb, dist + (size_t)(base + 128)*DHD, DHD, tid, nv1);
    stsB_<8,256>(E0, va, tid);
    stsB_<8,256>(E1, vb, tid);
    __syncthreads();

    float acc[2][8][4];
    float bacc[2][8][4];
    zeroacc(acc);

    const float* qwbase = g_qw + ((size_t)bh*LL + m0)*DHD;
    const size_t qwstride = (size_t)BHN*LL*DHD;

    // P0: KE half0 (A=Ka(k), B=E0)
    zeroacc(bacc);
    gemm64(Ka, E0, wm, wn, lane, bacc);
    writeQE(QEb, bacc, wm, wn, lane);
    __syncthreads();
    gatherDiag(QEb, acc, wm, wn, lane, 0, true);
    __syncthreads();

    // P1: KE half1 (A=Ka, B=E1). Ka free after.
    zeroacc(bacc);
    gemm64(Ka, E1, wm, wn, lane, bacc);
    writeQE(QEb, bacc, wm, wn, lane);
    __syncthreads();
    gatherDiag(QEb, acc, wm, wn, lane, 1, true);
    __syncthreads();

    // P2: QE half0 (A=Qf, B=E0). Prefetch qw0. E0 free after... (used again P2 only)
    ldgT<8,256>(va, qwbase, DHD, tid, 128);          // qw0
    zeroacc(bacc);
    gemm64(Qf, E0, wm, wn, lane, bacc);
    writeQE(QEb, bacc, wm, wn, lane);
    __syncthreads();
    gatherDiag(QEb, acc, wm, wn, lane, 0, false);
    __syncthreads();

    // P3: QE half1 (A=Qf, B=E1). Stage qw0->Ka, prefetch qw1.
    stsA_<8,256>(Ka, va, tid);                        // qw0 -> Ka
    ldgT<8,256>(vb, qwbase + qwstride, DHD, tid, 128);// qw1
    zeroacc(bacc);
    gemm64(Qf, E1, wm, wn, lane, bacc);
    writeQE(QEb, bacc, wm, wn, lane);
    __syncthreads();
    gatherDiag(QEb, acc, wm, wn, lane, 1, false);
    __syncthreads();

    // P4: QK (A=Qf, B=Kb). Stage qw1->E0, prefetch qw2. Scale+mask.
    stsA_<8,256>(E0, vb, tid);                        // qw1 -> E0
    ldgT<8,256>(va, qwbase + 2*qwstride, DHD, tid, 128);
    zeroacc(bacc);
    gemm64(Qf, Kb, wm, wn, lane, bacc);

    const float* mrow = mask + b*LL + n0;
    const int c0col = wn*64 + (lane & 3)*2;
    #pragma unroll
    for (int j = 0; j < 8; j++) {
        float2 mk = *(const float2*)(mrow + c0col + j*8);
        #pragma unroll
        for (int i = 0; i < 2; i++) {
            acc[i][j][0] = (acc[i][j][0] + bacc[i][j][0])*0.125f + mk.x;
            acc[i][j][1] = (acc[i][j][1] + bacc[i][j][1])*0.125f + mk.y;
            acc[i][j][2] = (acc[i][j][2] + bacc[i][j][2])*0.125f + mk.x;
            acc[i][j][3] = (acc[i][j][3] + bacc[i][j][3])*0.125f + mk.y;
        }
    }
    __syncthreads();

    // Bilinear passes: buffers {Ka, E0, E1, Ka, E0} hold qw0..qw4.
    unsigned* qbuf[5] = { Ka, E0, E1, Ka, E0 };
    const int r0 = wm*32 + (lane >> 2);

    #pragma unroll
    for (int i5 = 0; i5 < 5; i5++) {
        // stage qw_{i5+2} into its buffer; prefetch qw_{i5+3}
        if (i5 == 0) { stsA_<8,256>(E1, va, tid);      // qw2 -> E1
                       ldgT<8,256>(vb, qwbase + 3*qwstride, DHD, tid, 128); }
        if (i5 == 1) { stsA_<8,256>(Ka, vb, tid);      // qw3 -> Ka
                       ldgT<8,256>(va, qwbase + 4*qwstride, DHD, tid, 128); }
        if (i5 == 2) { stsA_<8,256>(E0, va, tid); }    // qw4 -> E0

        zeroacc(bacc);
        gemm64(qbuf[i5], Kb, wm, wn, lane, bacc);

        float ab = __ldg(&abv[i5*HH + h]);
        const float* stb = structm + (((size_t)(i5*BB + b)*LL + m0)*LL) + n0;
        #pragma unroll
        for (int i = 0; i < 2; i++)
            #pragma unroll
            for (int j = 0; j < 8; j++) {
                int rr = r0 + i*16, cc = c0col + j*8;
                float2 s0 = *(const float2*)(stb + (size_t)rr*LL + cc);
                float2 s1 = *(const float2*)(stb + (size_t)(rr+8)*LL + cc);
                acc[i][j][0] += (bacc[i][j][0] + ab)*s0.x;
                acc[i][j][1] += (bacc[i][j][1] + ab)*s0.y;
                acc[i][j][2] += (bacc[i][j][2] + ab)*s1.x;
                acc[i][j][3] += (bacc[i][j][3] + ab)*s1.y;
            }
        if (i5 < 4) __syncthreads();
    }

    float* sp = g_s + ((size_t)bh*LL + m0)*LL + n0;
    #pragma unroll
    for (int i = 0; i < 2; i++)
        #pragma unroll
        for (int j = 0; j < 8; j++) {
            int rr = r0 + i*16, cc = c0col + j*8;
            *(float2*)(sp + (size_t)rr*LL + cc)     = make_float2(acc[i][j][0], acc[i][j][1]);
            *(float2*)(sp + (size_t)(rr+8)*LL + cc) = make_float2(acc[i][j][2], acc[i][j][3]);
        }
}

// ============================================================
// K3: softmax (unchanged).
// ============================================================
__global__ __launch_bounds__(256) void softmax_kernel()
{
    const int warp = threadIdx.x >> 5, lane = threadIdx.x & 31;
    const size_t row = (size_t)blockIdx.x * 8 + warp;
    float* rp = g_s + row * LL;

    float4 v[8];
    float mx = -1e30f;
    #pragma unroll
    for (int k2 = 0; k2 < 8; k2++) {
        v[k2] = *(const float4*)&rp[(lane + k2*32)*4];
        mx = fmaxf(mx, fmaxf(fmaxf(v[k2].x, v[k2].y), fmaxf(v[k2].z, v[k2].w)));
    }
    #pragma unroll
    for (int o = 16; o > 0; o >>= 1) mx = fmaxf(mx, __shfl_xor_sync(0xffffffffu, mx, o));

    float s = 0.f;
    #pragma unroll
    for (int k2 = 0; k2 < 8; k2++) {
        v[k2].x = __expf(v[k2].x - mx);
        v[k2].y = __expf(v[k2].y - mx);
        v[k2].z = __expf(v[k2].z - mx);
        v[k2].w = __expf(v[k2].w - mx);
        s += v[k2].x + v[k2].y + v[k2].z + v[k2].w;
    }
    #pragma unroll
    for (int o = 16; o > 0; o >>= 1) s += __shfl_xor_sync(0xffffffffu, s, o);

    const float inv = 1.f / s;
    #pragma unroll
    for (int k2 = 0; k2 < 8; k2++) {
        v[k2].x *= inv; v[k2].y *= inv; v[k2].z *= inv; v[k2].w *= inv;
        *(float4*)&rp[(lane + k2*32)*4] = v[k2];
    }
}

// ============================================================
// K4: ctx = probs @ v, tf32, 2-stage pipelined. smem 96KB.
// ============================================================
__global__ __launch_bounds__(256) void pv_kernel(float* __restrict__ out)
{
    extern __shared__ unsigned smu[];
    unsigned* AF[2] = { smu,         smu + 12288 };
    unsigned* BF[2] = { smu + 8192,  smu + 20480 };

    const int bh = blockIdx.y;
    const int b = bh / HH, h = bh % HH;
    const int m0 = blockIdx.x * 128;
    const int tid = threadIdx.x, lane = tid & 31, wid = tid >> 5;

    const float* pb = g_s + (size_t)bh*LL*LL + (size_t)m0*LL;
    const float* vb = g_v + (size_t)bh*LL*DHD;

    float acc[8][4];
    #pragma unroll
    for (int j = 0; j < 8; j++)
        #pragma unroll
        for (int c = 0; c < 4; c++) acc[j][c] = 0.f;

    float4 vA[8], vB[4];
    ldgT<8,256>(vA, pb, LL, tid, 128);
    ldgBT<4,256,64>(vB, vb, DHD, tid);
    stsA_<8,256>(AF[0], vA, tid);
    stsBT_<4,256,64>(BF[0], vB, tid);
    ldgT<8,256>(vA, pb + 64, LL, tid, 128);
    ldgBT<4,256,64>(vB, vb + (size_t)64*DHD, DHD, tid);
    __syncthreads();

    for (int c = 0; c < 16; c++) {
        int cur = c & 1;
        if (c < 15) {
            stsA_<8,256>(AF[1-cur], vA, tid);
            stsBT_<4,256,64>(BF[1-cur], vB, tid);
        }
        if (c < 14) {
            ldgT<8,256>(vA, pb + (c+2)*64, LL, tid, 128);
            ldgBT<4,256,64>(vB, vb + (size_t)((c+2)*64)*DHD, DHD, tid);
        }
        gemm64n64(AF[cur], BF[cur], wid, lane, acc);
        __syncthreads();
    }

    const int r0 = wid*16 + (lane >> 2);
    const int c0 = (lane & 3)*2;
    #pragma unroll
    for (int j = 0; j < 8; j++) {
        int cc = c0 + j*8;
        #pragma unroll
        for (int half = 0; half < 2; half++) {
            int l = m0 + r0 + half*8;
            *(float2*)&out[((size_t)b*LL + l)*DD + h*DHD + cc] =
                make_float2(acc[j][half*2+0], acc[j][half*2+1]);
        }
    }
}

// ============================================================
extern "C" void kernel_launch(void* const* d_in, const int* in_sizes, int n_in,
                              void* d_out, int out_size)
{
    const float* hidden  = (const float*)d_in[0];
    const float* mask    = (const float*)d_in[1];
    const float* structm = (const float*)d_in[2];
    const float* Wq      = (const float*)d_in[3];
    const float* bq      = (const float*)d_in[4];
    const float* Wk      = (const float*)d_in[5];
    const float* bk      = (const float*)d_in[6];
    const float* Wv      = (const float*)d_in[7];
    const float* bv      = (const float*)d_in[8];
    const float* dist    = (const float*)d_in[9];
    const float* ssw     = (const float*)d_in[10];
    const float* abv     = (const float*)d_in[11];
    float* out = (float*)d_out;

    cudaFuncSetAttribute(qkv_kernel,    cudaFuncAttributeMaxDynamicSharedMemorySize, 131072);
    cudaFuncSetAttribute(qw_kernel,     cudaFuncAttributeMaxDynamicSharedMemorySize, 49152);
    cudaFuncSetAttribute(pv_kernel,     cudaFuncAttributeMaxDynamicSharedMemorySize, 98304);
    cudaFuncSetAttribute(scores_kernel, cudaFuncAttributeMaxDynamicSharedMemorySize, SMEM_SCORES);

    qkv_kernel    <<<dim3(6,16,3),  256, 131072>>>(hidden, Wq,bq, Wk,bk, Wv,bv);
    qw_kernel     <<<dim3(8,24,5),  256, 49152>>>(ssw);
    scores_kernel <<<dim3(24,8,8),  256, SMEM_SCORES>>>(mask, structm, dist, abv);
    softmax_kernel<<<3072,          256>>>();
    pv_kernel     <<<dim3(8,24),    256, 98304>>>(out);
}

// round 6
// speedup vs baseline: 1.7448x; 1.7448x over previous
#include <cuda_runtime.h>
#include <cuda_fp16.h>
#include <cstdint>

#define BB  2
#define LL  1024
#define DD  768
#define HH  12
#define DHD 64
#define BHN (BB*HH)

// ---- scratch ----
__device__ float g_q [BHN*LL*DHD];
__device__ float g_k [BHN*LL*DHD];
__device__ float g_v [BHN*LL*DHD];
__device__ float g_qw[5*BHN*LL*DHD];
__device__ float g_s [(size_t)BHN*LL*LL];

// ============================================================
// fp16 mma helpers (m16n8k16, f32 accum)
// ============================================================
__device__ __forceinline__ void mma16(float* c, const uint4 a, const uint2 b) {
    asm volatile(
        "mma.sync.aligned.m16n8k16.row.col.f32.f16.f16.f32 "
        "{%0,%1,%2,%3}, {%4,%5,%6,%7}, {%8,%9}, {%0,%1,%2,%3};"
        : "+f"(c[0]), "+f"(c[1]), "+f"(c[2]), "+f"(c[3])
        : "r"(a.x), "r"(a.y), "r"(a.z), "r"(a.w), "r"(b.x), "r"(b.y));
}

// ---- register-tile loaders (row-major 128x64, row stride ld) ----
template<int ITERS, int TPB>
__device__ __forceinline__ void ldgT4(float4* v, const float* __restrict__ src,
                                      int ld, int tid, int nvalid) {
    #pragma unroll
    for (int it = 0; it < ITERS; it++) {
        int idx = tid + it*TPB;
        int m = idx >> 4, k4 = idx & 15;
        v[it] = (m < nvalid) ? *(const float4*)(src + (size_t)m*ld + k4*4)
                             : make_float4(0.f, 0.f, 0.f, 0.f);
    }
}

// ---- STS to A-fragment fp16 layout: Af[ks(4)][mt(8)][lane(32)][4 h2] = 16KB ----
template<int ITERS, int TPB>
__device__ __forceinline__ void stsAh(__half2* dst, const float4* v, int tid) {
    #pragma unroll
    for (int it = 0; it < ITERS; it++) {
        int idx = tid + it*TPB;
        int m = idx >> 4, k4 = idx & 15;
        int mt = m >> 4, r = m & 15;
        int rbit = r >> 3, rlow = r & 7;
        {
            int k = k4*4;
            int ku = k & 15, ks = k >> 4, khigh = ku >> 3, kpair = (ku >> 1) & 3;
            dst[((ks*8 + mt)*32 + rlow*4 + kpair)*4 + rbit + 2*khigh] =
                __floats2half2_rn(v[it].x, v[it].y);
        }
        {
            int k = k4*4 + 2;
            int ku = k & 15, ks = k >> 4, khigh = ku >> 3, kpair = (ku >> 1) & 3;
            dst[((ks*8 + mt)*32 + rlow*4 + kpair)*4 + rbit + 2*khigh] =
                __floats2half2_rn(v[it].z, v[it].w);
        }
    }
}

// ---- STS to B-fragment fp16 layout from n-major regs: Bf[ks(4)][nt(16)][lane][2 h2] = 16KB ----
template<int ITERS, int TPB>
__device__ __forceinline__ void stsBh(__half2* dst, const float4* v, int tid) {
    #pragma unroll
    for (int it = 0; it < ITERS; it++) {
        int idx = tid + it*TPB;
        int n = idx >> 4, k4 = idx & 15;
        int nt = n >> 3, nlow = n & 7;
        {
            int k = k4*4;
            int ku = k & 15, ks = k >> 4;
            dst[((ks*16 + nt)*32 + nlow*4 + ((ku & 7) >> 1))*2 + (ku >> 3)] =
                __floats2half2_rn(v[it].x, v[it].y);
        }
        {
            int k = k4*4 + 2;
            int ku = k & 15, ks = k >> 4;
            dst[((ks*16 + nt)*32 + nlow*4 + ((ku & 7) >> 1))*2 + (ku >> 3)] =
                __floats2half2_rn(v[it].z, v[it].w);
        }
    }
}

// ---- fused stage: row-major 128x64 -> A-frag (256 threads) ----
__device__ __forceinline__ void stageAh(__half2* dst, const float* __restrict__ src,
                                        int ld, int tid) {
    float4 v[8];
    ldgT4<8,256>(v, src, ld, tid, 128);
    stsAh<8,256>(dst, v, tid);
}

// ---- fused stage: k-major 64xN (stride ldn) -> B-frag, transposing (256 threads) ----
template<int N>
__device__ __forceinline__ void stageBTh(__half2* dst, const float* __restrict__ src,
                                         int ldn, int tid) {
    constexpr int NT = N / 8;
    constexpr int F4 = N / 4;
    constexpr int ITEMS = 32 * F4;           // 32 k-pairs x F4 n-quads
    #pragma unroll
    for (int it = 0; it < ITEMS/256; it++) {
        int idx = tid + it*256;
        int k2 = idx / F4, nq = idx % F4;
        int k = k2*2;
        float4 u = *(const float4*)(src + (size_t)k*ldn + nq*4);
        float4 w = *(const float4*)(src + (size_t)(k+1)*ldn + nq*4);
        int ku = k & 15, ks = k >> 4, reg = ku >> 3;
        int kl = (ku & 7) >> 1;
        float uu[4] = {u.x,u.y,u.z,u.w};
        float ww[4] = {w.x,w.y,w.z,w.w};
        #pragma unroll
        for (int c2 = 0; c2 < 4; c2++) {
            int n = nq*4 + c2;
            int nt = n >> 3;
            dst[((ks*NT + nt)*32 + (n & 7)*4 + kl)*2 + reg] =
                __floats2half2_rn(uu[c2], ww[c2]);
        }
    }
}

// ---- 128x128x64 pass, 8 warps (warp tile 32x64) ----
__device__ __forceinline__ void gemm64h(const __half2* __restrict__ Af,
                                        const __half2* __restrict__ Bf,
                                        int wm, int wn, int lane, float bacc[2][8][4]) {
    const uint4* A4 = (const uint4*)Af;
    const uint2* B2 = (const uint2*)Bf;
    #pragma unroll
    for (int ks = 0; ks < 4; ks++) {
        uint4 a0 = A4[(ks*8 + wm*2 + 0)*32 + lane];
        uint4 a1 = A4[(ks*8 + wm*2 + 1)*32 + lane];
        #pragma unroll
        for (int j = 0; j < 8; j++) {
            uint2 b = B2[(ks*16 + wn*8 + j)*32 + lane];
            mma16(bacc[0][j], a0, b);
            mma16(bacc[1][j], a1, b);
        }
    }
}

// ---- 128x64x64 pass, 8 warps (warp = one 16-row group) ----
__device__ __forceinline__ void gemm64n64h(const __half2* __restrict__ Af,
                                           const __half2* __restrict__ Bf,
                                           int wid, int lane, float acc[8][4]) {
    const uint4* A4 = (const uint4*)Af;
    const uint2* B2 = (const uint2*)Bf;
    #pragma unroll
    for (int ks = 0; ks < 4; ks++) {
        uint4 a = A4[(ks*8 + wid)*32 + lane];
        #pragma unroll
        for (int j = 0; j < 8; j++) {
            uint2 b = B2[(ks*8 + j)*32 + lane];
            mma16(acc[j], a, b);
        }
    }
}

// ---- 128x128x64 pass, 16 warps (warp tile 32x32) — scores kernel ----
__device__ __forceinline__ void gemm32h(const __half2* __restrict__ Af,
                                        const __half2* __restrict__ Bf,
                                        int wm, int wn, int lane, float bacc[2][4][4]) {
    const uint4* A4 = (const uint4*)Af;
    const uint2* B2 = (const uint2*)Bf;
    #pragma unroll
    for (int ks = 0; ks < 4; ks++) {
        uint4 a0 = A4[(ks*8 + wm*2 + 0)*32 + lane];
        uint4 a1 = A4[(ks*8 + wm*2 + 1)*32 + lane];
        #pragma unroll
        for (int j = 0; j < 4; j++) {
            uint2 b = B2[(ks*16 + wn*4 + j)*32 + lane];
            mma16(bacc[0][j], a0, b);
            mma16(bacc[1][j], a1, b);
        }
    }
}

__device__ __forceinline__ void zero32(float a[2][4][4]) {
    #pragma unroll
    for (int i = 0; i < 2; i++)
        #pragma unroll
        for (int j = 0; j < 4; j++)
            #pragma unroll
            for (int c = 0; c < 4; c++) a[i][j][c] = 0.f;
}

// ============================================================
// K1: QKV projection (fp16 mma, 256 thr)
// ============================================================
__global__ __launch_bounds__(256) void qkv_kernel(
    const float* __restrict__ hidden,
    const float* __restrict__ Wq, const float* __restrict__ bq,
    const float* __restrict__ Wk, const float* __restrict__ bk,
    const float* __restrict__ Wv, const float* __restrict__ bv)
{
    extern __shared__ __align__(16) char smraw[];
    __half2* Af = (__half2*)smraw;
    __half2* Bf = (__half2*)(smraw + 16384);

    const int mat = blockIdx.z;
    const float* W    = (mat==0) ? Wq : (mat==1 ? Wk : Wv);
    const float* bias = (mat==0) ? bq : (mat==1 ? bk : bv);
    float* outp       = (mat==0) ? g_q : (mat==1 ? g_k : g_v);

    const int n0 = blockIdx.x * 128;
    const int m0 = blockIdx.y * 128;
    const int tid = threadIdx.x, lane = tid & 31, wid = tid >> 5;
    const int wm = wid & 3, wn = wid >> 2;

    float acc[2][8][4];
    #pragma unroll
    for (int i = 0; i < 2; i++)
        #pragma unroll
        for (int j = 0; j < 8; j++)
            #pragma unroll
            for (int c = 0; c < 4; c++) acc[i][j][c] = 0.f;

    for (int kc0 = 0; kc0 < DD; kc0 += 64) {
        stageAh(Af, hidden + (size_t)m0*DD + kc0, DD, tid);
        stageBTh<128>(Bf, W + (size_t)kc0*DD + n0, DD, tid);
        __syncthreads();
        gemm64h(Af, Bf, wm, wn, lane, acc);
        __syncthreads();
    }

    const int r0 = wm*32 + (lane >> 2);
    const int c0 = wn*64 + (lane & 3)*2;
    #pragma unroll
    for (int i = 0; i < 2; i++)
        #pragma unroll
        for (int j = 0; j < 8; j++) {
            int cg = n0 + c0 + j*8;
            int h = cg >> 6, dh = cg & 63;
            float2 bb = *(const float2*)(bias + cg);
            #pragma unroll
            for (int half = 0; half < 2; half++) {
                int rg = m0 + r0 + i*16 + half*8;
                int b = rg >> 10, l = rg & 1023;
                *(float2*)&outp[((b*HH + h)*LL + l)*DHD + dh] =
                    make_float2(acc[i][j][half*2+0] + bb.x,
                                acc[i][j][half*2+1] + bb.y);
            }
        }
}

// ============================================================
// K1b: qw precompute (fp16 mma, 256 thr)
// ============================================================
__global__ __launch_bounds__(256) void qw_kernel(const float* __restrict__ ssw)
{
    extern __shared__ __align__(16) char smraw[];
    __half2* Af = (__half2*)smraw;
    __half2* Bf = (__half2*)(smraw + 16384);

    const int i5 = blockIdx.z;
    const int bh = blockIdx.y;
    const int h  = bh % HH;
    const int m0 = blockIdx.x * 128;
    const int tid = threadIdx.x, lane = tid & 31, wid = tid >> 5;

    stageAh(Af, g_q + (size_t)(bh*LL + m0)*DHD, DHD, tid);
    stageBTh<64>(Bf, ssw + (size_t)(i5*HH + h)*DHD*DHD, DHD, tid);
    __syncthreads();

    float acc[8][4];
    #pragma unroll
    for (int j = 0; j < 8; j++)
        #pragma unroll
        for (int c = 0; c < 4; c++) acc[j][c] = 0.f;

    gemm64n64h(Af, Bf, wid, lane, acc);

    float* ob = g_qw + ((size_t)(i5*BHN + bh)*LL + m0)*DHD;
    const int r0 = wid*16 + (lane >> 2);
    const int c0 = (lane & 3)*2;
    #pragma unroll
    for (int j = 0; j < 8; j++) {
        int cc = c0 + j*8;
        *(float2*)(ob + (size_t)r0*DHD + cc)     = make_float2(acc[j][0], acc[j][1]);
        *(float2*)(ob + (size_t)(r0+8)*DHD + cc) = make_float2(acc[j][2], acc[j][3]);
    }
}

// ============================================================
// K2: fused scores (fp16 mma, 512 thr, 16 warps, warp tile 32x32)
// smem: Q(16K) Kb(16K) Ka(16K) E(16K) + QEb f32 128x132 (67.6K) = 133120
// ============================================================
#define SC_SMEM 133120

__global__ __launch_bounds__(512, 1) void scores_kernel(
    const float* __restrict__ mask,
    const float* __restrict__ structm,
    const float* __restrict__ dist,
    const float* __restrict__ abv)
{
    extern __shared__ __align__(16) char smraw[];
    __half2* Q  = (__half2*)smraw;
    __half2* Kb = (__half2*)(smraw + 16384);
    __half2* Ka = (__half2*)(smraw + 32768);
    __half2* E  = (__half2*)(smraw + 49152);
    float*  QEb = (float*)(smraw + 65536);

    const int bh = blockIdx.x, kt = blockIdx.y, qt = blockIdx.z;
    const int b = bh / HH, h = bh % HH;
    const int m0 = qt*128, n0 = kt*128;
    const int tid = threadIdx.x, lane = tid & 31, wid = tid >> 5;
    const int wm = wid & 3, wn = wid >> 2;
    const int r0 = wm*32 + (lane >> 2);
    const int c0 = wn*32 + (lane & 3)*2;

    const int base = (qt - kt)*128 + 896;
    int nv1 = 1919 - base; if (nv1 > 128) nv1 = 128;

    float4 vA[4], vB[4];
    // prologue staging
    ldgT4<4,512>(vA, g_q + (size_t)(bh*LL + m0)*DHD, DHD, tid, 128);
    ldgT4<4,512>(vB, g_k + (size_t)(bh*LL + n0)*DHD, DHD, tid, 128);
    stsAh<4,512>(Q, vA, tid);
    stsAh<4,512>(Ka, vB, tid);
    stsBh<4,512>(Kb, vB, tid);
    ldgT4<4,512>(vA, dist + (size_t)base*DHD, DHD, tid, 128);
    stsBh<4,512>(E, vA, tid);
    ldgT4<4,512>(vB, dist + (size_t)(base + 128)*DHD, DHD, tid, nv1);  // E1 in regs
    __syncthreads();

    float acc[2][4][4];
    float bacc[2][4][4];
    zero32(acc);

    const float* qwbase = g_qw + ((size_t)bh*LL + m0)*DHD;
    const size_t qwstr = (size_t)BHN*LL*DHD;

    // ---- macro-ish lambdas ----
    auto writeQE = [&]() {
        #pragma unroll
        for (int i = 0; i < 2; i++)
            #pragma unroll
            for (int j = 0; j < 4; j++) {
                int rr = r0 + i*16, cc = c0 + j*8;
                *(float2*)(QEb + rr*132 + cc)     = make_float2(bacc[i][j][0], bacc[i][j][1]);
                *(float2*)(QEb + (rr+8)*132 + cc) = make_float2(bacc[i][j][2], bacc[i][j][3]);
            }
    };
    auto gather = [&](int off, bool useCol) {
        #pragma unroll
        for (int i = 0; i < 2; i++)
            #pragma unroll
            for (int j = 0; j < 4; j++) {
                int rr = r0 + i*16, cc = c0 + j*8;
                #pragma unroll
                for (int c2 = 0; c2 < 4; c2++) {
                    int R = rr + (c2 >> 1)*8;
                    int C = cc + (c2 & 1);
                    int J = R - C + off;
                    if ((unsigned)J < 128u) {
                        int rowi = useCol ? C : R;
                        acc[i][j][c2] += QEb[rowi*132 + J];
                    }
                }
            }
    };

    // P0: KE half0
    zero32(bacc); gemm32h(Ka, E, wm, wn, lane, bacc);
    writeQE(); __syncthreads();
    gather(127, true); __syncthreads();

    // P1: QE half0; then restage E <- half1, prefetch qw0
    zero32(bacc); gemm32h(Q, E, wm, wn, lane, bacc);
    writeQE(); __syncthreads();
    gather(127, false);
    stsBh<4,512>(E, vB, tid);                       // E1
    ldgT4<4,512>(vA, qwbase, DHD, tid, 128);        // qw0
    __syncthreads();

    // P2: KE half1; stage qw0->Ka, prefetch qw1
    zero32(bacc); gemm32h(Ka, E, wm, wn, lane, bacc);
    writeQE(); __syncthreads();
    gather(-1, true);
    stsAh<4,512>(Ka, vA, tid);                      // qw0
    ldgT4<4,512>(vB, qwbase + qwstr, DHD, tid, 128);// qw1
    __syncthreads();

    // P3: QE half1; stage qw1->E, prefetch qw2
    zero32(bacc); gemm32h(Q, E, wm, wn, lane, bacc);
    writeQE(); __syncthreads();
    gather(-1, false);
    stsAh<4,512>(E, vB, tid);                       // qw1
    ldgT4<4,512>(vA, qwbase + 2*qwstr, DHD, tid, 128);
    __syncthreads();

    // P4: QK; scale + mask
    zero32(bacc); gemm32h(Q, Kb, wm, wn, lane, bacc);
    {
        const float* mrow = mask + b*LL + n0;
        #pragma unroll
        for (int j = 0; j < 4; j++) {
            float2 mk = *(const float2*)(mrow + c0 + j*8);
            #pragma unroll
            for (int i = 0; i < 2; i++) {
                acc[i][j][0] = (acc[i][j][0] + bacc[i][j][0])*0.125f + mk.x;
                acc[i][j][1] = (acc[i][j][1] + bacc[i][j][1])*0.125f + mk.y;
                acc[i][j][2] = (acc[i][j][2] + bacc[i][j][2])*0.125f + mk.x;
                acc[i][j][3] = (acc[i][j][3] + bacc[i][j][3])*0.125f + mk.y;
            }
        }
    }
    __syncthreads();
    stsAh<4,512>(Q, vA, tid);                       // qw2 -> Q
    ldgT4<4,512>(vB, qwbase + 3*qwstr, DHD, tid, 128);

    // bilinear epilogue helper
    auto structEpi = [&](int i5) {
        float ab = __ldg(&abv[i5*HH + h]);
        const float* stb = structm + (((size_t)(i5*BB + b)*LL + m0)*LL) + n0;
        #pragma unroll
        for (int i = 0; i < 2; i++)
            #pragma unroll
            for (int j = 0; j < 4; j++) {
                int rr = r0 + i*16, cc = c0 + j*8;
                float2 s0 = *(const float2*)(stb + (size_t)rr*LL + cc);
                float2 s1 = *(const float2*)(stb + (size_t)(rr+8)*LL + cc);
                acc[i][j][0] += (bacc[i][j][0] + ab)*s0.x;
                acc[i][j][1] += (bacc[i][j][1] + ab)*s0.y;
                acc[i][j][2] += (bacc[i][j][2] + ab)*s1.x;
                acc[i][j][3] += (bacc[i][j][3] + ab)*s1.y;
            }
    };

    // P5: bilinear0 (qw0 in Ka)
    zero32(bacc); gemm32h(Ka, Kb, wm, wn, lane, bacc);
    structEpi(0);
    __syncthreads();
    stsAh<4,512>(Ka, vB, tid);                      // qw3 -> Ka
    ldgT4<4,512>(vA, qwbase + 4*qwstr, DHD, tid, 128);

    // P6: bilinear1 (qw1 in E)
    zero32(bacc); gemm32h(E, Kb, wm, wn, lane, bacc);
    structEpi(1);
    __syncthreads();
    stsAh<4,512>(E, vA, tid);                       // qw4 -> E

    // P7: bilinear2 (qw2 in Q)
    zero32(bacc); gemm32h(Q, Kb, wm, wn, lane, bacc);
    structEpi(2);
    __syncthreads();

    // P8: bilinear3 (qw3 in Ka)
    zero32(bacc); gemm32h(Ka, Kb, wm, wn, lane, bacc);
    structEpi(3);
    __syncthreads();

    // P9: bilinear4 (qw4 in E)
    zero32(bacc); gemm32h(E, Kb, wm, wn, lane, bacc);
    structEpi(4);

    // store scores
    float* sp = g_s + ((size_t)bh*LL + m0)*LL + n0;
    #pragma unroll
    for (int i = 0; i < 2; i++)
        #pragma unroll
        for (int j = 0; j < 4; j++) {
            int rr = r0 + i*16, cc = c0 + j*8;
            *(float2*)(sp + (size_t)rr*LL + cc)     = make_float2(acc[i][j][0], acc[i][j][1]);
            *(float2*)(sp + (size_t)(rr+8)*LL + cc) = make_float2(acc[i][j][2], acc[i][j][3]);
        }
}

// ============================================================
// K3: softmax (unchanged)
// ============================================================
__global__ __launch_bounds__(256) void softmax_kernel()
{
    const int warp = threadIdx.x >> 5, lane = threadIdx.x & 31;
    const size_t row = (size_t)blockIdx.x * 8 + warp;
    float* rp = g_s + row * LL;

    float4 v[8];
    float mx = -1e30f;
    #pragma unroll
    for (int k2 = 0; k2 < 8; k2++) {
        v[k2] = *(const float4*)&rp[(lane + k2*32)*4];
        mx = fmaxf(mx, fmaxf(fmaxf(v[k2].x, v[k2].y), fmaxf(v[k2].z, v[k2].w)));
    }
    #pragma unroll
    for (int o = 16; o > 0; o >>= 1) mx = fmaxf(mx, __shfl_xor_sync(0xffffffffu, mx, o));

    float s = 0.f;
    #pragma unroll
    for (int k2 = 0; k2 < 8; k2++) {
        v[k2].x = __expf(v[k2].x - mx);
        v[k2].y = __expf(v[k2].y - mx);
        v[k2].z = __expf(v[k2].z - mx);
        v[k2].w = __expf(v[k2].w - mx);
        s += v[k2].x + v[k2].y + v[k2].z + v[k2].w;
    }
    #pragma unroll
    for (int o = 16; o > 0; o >>= 1) s += __shfl_xor_sync(0xffffffffu, s, o);

    const float inv = 1.f / s;
    #pragma unroll
    for (int k2 = 0; k2 < 8; k2++) {
        v[k2].x *= inv; v[k2].y *= inv; v[k2].z *= inv; v[k2].w *= inv;
        *(float4*)&rp[(lane + k2*32)*4] = v[k2];
    }
}

// ============================================================
// K4: ctx = probs @ v (fp16 mma, 256 thr)
// ============================================================
__global__ __launch_bounds__(256) void pv_kernel(float* __restrict__ out)
{
    extern __shared__ __align__(16) char smraw[];
    __half2* Af = (__half2*)smraw;
    __half2* Bf = (__half2*)(smraw + 16384);

    const int bh = blockIdx.y;
    const int b = bh / HH, h = bh % HH;
    const int m0 = blockIdx.x * 128;
    const int tid = threadIdx.x, lane = tid & 31, wid = tid >> 5;

    const float* pb = g_s + (size_t)bh*LL*LL + (size_t)m0*LL;
    const float* vb = g_v + (size_t)bh*LL*DHD;

    float acc[8][4];
    #pragma unroll
    for (int j = 0; j < 8; j++)
        #pragma unroll
        for (int c = 0; c < 4; c++) acc[j][c] = 0.f;

    for (int kc0 = 0; kc0 < LL; kc0 += 64) {
        stageAh(Af, pb + kc0, LL, tid);
        stageBTh<64>(Bf, vb + (size_t)kc0*DHD, DHD, tid);
        __syncthreads();
        gemm64n64h(Af, Bf, wid, lane, acc);
        __syncthreads();
    }

    const int r0 = wid*16 + (lane >> 2);
    const int c0 = (lane & 3)*2;
    #pragma unroll
    for (int j = 0; j < 8; j++) {
        int cc = c0 + j*8;
        #pragma unroll
        for (int half = 0; half < 2; half++) {
            int l = m0 + r0 + half*8;
            *(float2*)&out[((size_t)b*LL + l)*DD + h*DHD + cc] =
                make_float2(acc[j][half*2+0], acc[j][half*2+1]);
        }
    }
}

// ============================================================
extern "C" void kernel_launch(void* const* d_in, const int* in_sizes, int n_in,
                              void* d_out, int out_size)
{
    const float* hidden  = (const float*)d_in[0];
    const float* mask    = (const float*)d_in[1];
    const float* structm = (const float*)d_in[2];
    const float* Wq      = (const float*)d_in[3];
    const float* bq      = (const float*)d_in[4];
    const float* Wk      = (const float*)d_in[5];
    const float* bk      = (const float*)d_in[6];
    const float* Wv      = (const float*)d_in[7];
    const float* bv      = (const float*)d_in[8];
    const float* dist    = (const float*)d_in[9];
    const float* ssw     = (const float*)d_in[10];
    const float* abv     = (const float*)d_in[11];
    float* out = (float*)d_out;

    cudaFuncSetAttribute(qkv_kernel,    cudaFuncAttributeMaxDynamicSharedMemorySize, 32768);
    cudaFuncSetAttribute(qw_kernel,     cudaFuncAttributeMaxDynamicSharedMemorySize, 24576);
    cudaFuncSetAttribute(pv_kernel,     cudaFuncAttributeMaxDynamicSharedMemorySize, 24576);
    cudaFuncSetAttribute(scores_kernel, cudaFuncAttributeMaxDynamicSharedMemorySize, SC_SMEM);

    qkv_kernel    <<<dim3(6,16,3),  256, 32768>>>(hidden, Wq,bq, Wk,bk, Wv,bv);
    qw_kernel     <<<dim3(8,24,5),  256, 24576>>>(ssw);
    scores_kernel <<<dim3(24,8,8),  512, SC_SMEM>>>(mask, structm, dist, abv);
    softmax_kernel<<<3072,          256>>>();
    pv_kernel     <<<dim3(8,24),    256, 24576>>>(out);
}

// round 7
// speedup vs baseline: 1.9508x; 1.1181x over previous
#include <cuda_runtime.h>
#include <cuda_fp16.h>
#include <cstdint>

#define BB  2
#define LL  1024
#define DD  768
#define HH  12
#define DHD 64
#define BHN (BB*HH)

// ---- scratch ----
__device__ float g_q [BHN*LL*DHD];
__device__ float g_k [BHN*LL*DHD];
__device__ float g_v [BHN*LL*DHD];
__device__ float g_qw[5*BHN*LL*DHD];
__device__ float g_s [(size_t)BHN*LL*LL];
__device__ float g_mx [BHN*LL];
__device__ float g_inv[BHN*LL];

// ============================================================
// fp16 mma helpers (m16n8k16, f32 accum)
// ============================================================
__device__ __forceinline__ void mma16(float* c, const uint4 a, const uint2 b) {
    asm volatile(
        "mma.sync.aligned.m16n8k16.row.col.f32.f16.f16.f32 "
        "{%0,%1,%2,%3}, {%4,%5,%6,%7}, {%8,%9}, {%0,%1,%2,%3};"
        : "+f"(c[0]), "+f"(c[1]), "+f"(c[2]), "+f"(c[3])
        : "r"(a.x), "r"(a.y), "r"(a.z), "r"(a.w), "r"(b.x), "r"(b.y));
}

// ---- register-tile loaders (row-major 128x64, row stride ld) ----
template<int ITERS, int TPB>
__device__ __forceinline__ void ldgT4(float4* v, const float* __restrict__ src,
                                      int ld, int tid, int nvalid) {
    #pragma unroll
    for (int it = 0; it < ITERS; it++) {
        int idx = tid + it*TPB;
        int m = idx >> 4, k4 = idx & 15;
        v[it] = (m < nvalid) ? *(const float4*)(src + (size_t)m*ld + k4*4)
                             : make_float4(0.f, 0.f, 0.f, 0.f);
    }
}

// ---- STS to A-fragment fp16 layout: Af[ks(4)][mt(8)][lane(32)][4 h2] = 16KB ----
template<int ITERS, int TPB>
__device__ __forceinline__ void stsAh(__half2* dst, const float4* v, int tid) {
    #pragma unroll
    for (int it = 0; it < ITERS; it++) {
        int idx = tid + it*TPB;
        int m = idx >> 4, k4 = idx & 15;
        int mt = m >> 4, r = m & 15;
        int rbit = r >> 3, rlow = r & 7;
        {
            int k = k4*4;
            int ku = k & 15, ks = k >> 4, khigh = ku >> 3, kpair = (ku >> 1) & 3;
            dst[((ks*8 + mt)*32 + rlow*4 + kpair)*4 + rbit + 2*khigh] =
                __floats2half2_rn(v[it].x, v[it].y);
        }
        {
            int k = k4*4 + 2;
            int ku = k & 15, ks = k >> 4, khigh = ku >> 3, kpair = (ku >> 1) & 3;
            dst[((ks*8 + mt)*32 + rlow*4 + kpair)*4 + rbit + 2*khigh] =
                __floats2half2_rn(v[it].z, v[it].w);
        }
    }
}

// ---- STS to B-fragment fp16 layout: Bf[ks(4)][nt(16)][lane][2 h2] = 16KB ----
template<int ITERS, int TPB>
__device__ __forceinline__ void stsBh(__half2* dst, const float4* v, int tid) {
    #pragma unroll
    for (int it = 0; it < ITERS; it++) {
        int idx = tid + it*TPB;
        int n = idx >> 4, k4 = idx & 15;
        int nt = n >> 3, nlow = n & 7;
        {
            int k = k4*4;
            int ku = k & 15, ks = k >> 4;
            dst[((ks*16 + nt)*32 + nlow*4 + ((ku & 7) >> 1))*2 + (ku >> 3)] =
                __floats2half2_rn(v[it].x, v[it].y);
        }
        {
            int k = k4*4 + 2;
            int ku = k & 15, ks = k >> 4;
            dst[((ks*16 + nt)*32 + nlow*4 + ((ku & 7) >> 1))*2 + (ku >> 3)] =
                __floats2half2_rn(v[it].z, v[it].w);
        }
    }
}

// ---- fused stage: row-major 128x64 -> A-frag (256 threads) ----
__device__ __forceinline__ void stageAh(__half2* dst, const float* __restrict__ src,
                                        int ld, int tid) {
    float4 v[8];
    ldgT4<8,256>(v, src, ld, tid, 128);
    stsAh<8,256>(dst, v, tid);
}

// A-frag staging with fused exp(x - rowmax): for pv probs
__device__ __forceinline__ void stageAhExp(__half2* dst, const float* __restrict__ src,
                                           int ld, int tid, const float* __restrict__ rm) {
    float4 v[8];
    ldgT4<8,256>(v, src, ld, tid, 128);
    #pragma unroll
    for (int it = 0; it < 8; it++) {
        int m = (tid + it*256) >> 4;
        float mm = rm[m];
        v[it].x = __expf(v[it].x - mm);
        v[it].y = __expf(v[it].y - mm);
        v[it].z = __expf(v[it].z - mm);
        v[it].w = __expf(v[it].w - mm);
    }
    stsAh<8,256>(dst, v, tid);
}

// ---- fused stage: k-major 64xN (stride ldn) -> B-frag, transposing (256 thr) ----
template<int N>
__device__ __forceinline__ void stageBTh(__half2* dst, const float* __restrict__ src,
                                         int ldn, int tid) {
    constexpr int NT = N / 8;
    constexpr int F4 = N / 4;
    constexpr int ITEMS = 32 * F4;
    #pragma unroll
    for (int it = 0; it < ITEMS/256; it++) {
        int idx = tid + it*256;
        int k2 = idx / F4, nq = idx % F4;
        int k = k2*2;
        float4 u = *(const float4*)(src + (size_t)k*ldn + nq*4);
        float4 w = *(const float4*)(src + (size_t)(k+1)*ldn + nq*4);
        int ku = k & 15, ks = k >> 4, reg = ku >> 3;
        int kl = (ku & 7) >> 1;
        float uu[4] = {u.x,u.y,u.z,u.w};
        float ww[4] = {w.x,w.y,w.z,w.w};
        #pragma unroll
        for (int c2 = 0; c2 < 4; c2++) {
            int n = nq*4 + c2;
            int nt = n >> 3;
            dst[((ks*NT + nt)*32 + (n & 7)*4 + kl)*2 + reg] =
                __floats2half2_rn(uu[c2], ww[c2]);
        }
    }
}

// ---- 128x128x64 pass, 8 warps (warp tile 32x64) ----
__device__ __forceinline__ void gemm64h(const __half2* __restrict__ Af,
                                        const __half2* __restrict__ Bf,
                                        int wm, int wn, int lane, float bacc[2][8][4]) {
    const uint4* A4 = (const uint4*)Af;
    const uint2* B2 = (const uint2*)Bf;
    #pragma unroll
    for (int ks = 0; ks < 4; ks++) {
        uint4 a0 = A4[(ks*8 + wm*2 + 0)*32 + lane];
        uint4 a1 = A4[(ks*8 + wm*2 + 1)*32 + lane];
        #pragma unroll
        for (int j = 0; j < 8; j++) {
            uint2 b = B2[(ks*16 + wn*8 + j)*32 + lane];
            mma16(bacc[0][j], a0, b);
            mma16(bacc[1][j], a1, b);
        }
    }
}

// ---- 128x64x64 pass, 8 warps ----
__device__ __forceinline__ void gemm64n64h(const __half2* __restrict__ Af,
                                           const __half2* __restrict__ Bf,
                                           int wid, int lane, float acc[8][4]) {
    const uint4* A4 = (const uint4*)Af;
    const uint2* B2 = (const uint2*)Bf;
    #pragma unroll
    for (int ks = 0; ks < 4; ks++) {
        uint4 a = A4[(ks*8 + wid)*32 + lane];
        #pragma unroll
        for (int j = 0; j < 8; j++) {
            uint2 b = B2[(ks*8 + j)*32 + lane];
            mma16(acc[j], a, b);
        }
    }
}

// ---- 128x128x64 pass, 16 warps (warp tile 32x32) ----
__device__ __forceinline__ void gemm32h(const __half2* __restrict__ Af,
                                        const __half2* __restrict__ Bf,
                                        int wm, int wn, int lane, float bacc[2][4][4]) {
    const uint4* A4 = (const uint4*)Af;
    const uint2* B2 = (const uint2*)Bf;
    #pragma unroll
    for (int ks = 0; ks < 4; ks++) {
        uint4 a0 = A4[(ks*8 + wm*2 + 0)*32 + lane];
        uint4 a1 = A4[(ks*8 + wm*2 + 1)*32 + lane];
        #pragma unroll
        for (int j = 0; j < 4; j++) {
            uint2 b = B2[(ks*16 + wn*4 + j)*32 + lane];
            mma16(bacc[0][j], a0, b);
            mma16(bacc[1][j], a1, b);
        }
    }
}

__device__ __forceinline__ void zero32(float a[2][4][4]) {
    #pragma unroll
    for (int i = 0; i < 2; i++)
        #pragma unroll
        for (int j = 0; j < 4; j++)
            #pragma unroll
            for (int c = 0; c < 4; c++) a[i][j][c] = 0.f;
}

// ============================================================
// K1: QKV projection (fp16 mma, 256 thr) — unchanged from R6
// ============================================================
__global__ __launch_bounds__(256) void qkv_kernel(
    const float* __restrict__ hidden,
    const float* __restrict__ Wq, const float* __restrict__ bq,
    const float* __restrict__ Wk, const float* __restrict__ bk,
    const float* __restrict__ Wv, const float* __restrict__ bv)
{
    extern __shared__ __align__(16) char smraw[];
    __half2* Af = (__half2*)smraw;
    __half2* Bf = (__half2*)(smraw + 16384);

    const int mat = blockIdx.z;
    const float* W    = (mat==0) ? Wq : (mat==1 ? Wk : Wv);
    const float* bias = (mat==0) ? bq : (mat==1 ? bk : bv);
    float* outp       = (mat==0) ? g_q : (mat==1 ? g_k : g_v);

    const int n0 = blockIdx.x * 128;
    const int m0 = blockIdx.y * 128;
    const int tid = threadIdx.x, lane = tid & 31, wid = tid >> 5;
    const int wm = wid & 3, wn = wid >> 2;

    float acc[2][8][4];
    #pragma unroll
    for (int i = 0; i < 2; i++)
        #pragma unroll
        for (int j = 0; j < 8; j++)
            #pragma unroll
            for (int c = 0; c < 4; c++) acc[i][j][c] = 0.f;

    for (int kc0 = 0; kc0 < DD; kc0 += 64) {
        stageAh(Af, hidden + (size_t)m0*DD + kc0, DD, tid);
        stageBTh<128>(Bf, W + (size_t)kc0*DD + n0, DD, tid);
        __syncthreads();
        gemm64h(Af, Bf, wm, wn, lane, acc);
        __syncthreads();
    }

    const int r0 = wm*32 + (lane >> 2);
    const int c0 = wn*64 + (lane & 3)*2;
    #pragma unroll
    for (int i = 0; i < 2; i++)
        #pragma unroll
        for (int j = 0; j < 8; j++) {
            int cg = n0 + c0 + j*8;
            int h = cg >> 6, dh = cg & 63;
            float2 bb = *(const float2*)(bias + cg);
            #pragma unroll
            for (int half = 0; half < 2; half++) {
                int rg = m0 + r0 + i*16 + half*8;
                int b = rg >> 10, l = rg & 1023;
                *(float2*)&outp[((b*HH + h)*LL + l)*DHD + dh] =
                    make_float2(acc[i][j][half*2+0] + bb.x,
                                acc[i][j][half*2+1] + bb.y);
            }
        }
}

// ============================================================
// K1b: qw precompute (fp16 mma, 256 thr) — unchanged from R6
// ============================================================
__global__ __launch_bounds__(256) void qw_kernel(const float* __restrict__ ssw)
{
    extern __shared__ __align__(16) char smraw[];
    __half2* Af = (__half2*)smraw;
    __half2* Bf = (__half2*)(smraw + 16384);

    const int i5 = blockIdx.z;
    const int bh = blockIdx.y;
    const int h  = bh % HH;
    const int m0 = blockIdx.x * 128;
    const int tid = threadIdx.x, lane = tid & 31, wid = tid >> 5;

    stageAh(Af, g_q + (size_t)(bh*LL + m0)*DHD, DHD, tid);
    stageBTh<64>(Bf, ssw + (size_t)(i5*HH + h)*DHD*DHD, DHD, tid);
    __syncthreads();

    float acc[8][4];
    #pragma unroll
    for (int j = 0; j < 8; j++)
        #pragma unroll
        for (int c = 0; c < 4; c++) acc[j][c] = 0.f;

    gemm64n64h(Af, Bf, wid, lane, acc);

    float* ob = g_qw + ((size_t)(i5*BHN + bh)*LL + m0)*DHD;
    const int r0 = wid*16 + (lane >> 2);
    const int c0 = (lane & 3)*2;
    #pragma unroll
    for (int j = 0; j < 8; j++) {
        int cc = c0 + j*8;
        *(float2*)(ob + (size_t)r0*DHD + cc)     = make_float2(acc[j][0], acc[j][1]);
        *(float2*)(ob + (size_t)(r0+8)*DHD + cc) = make_float2(acc[j][2], acc[j][3]);
    }
}

// ============================================================
// K2: fused scores — restructured: 7 barriers, double fp16 QEb,
// struct/mask register prefetch.
// smem: Q|Kb|Ka|E0|E1 (16K ea) + 2x QEb fp16 (128x132) = 149504
// ============================================================
#define SC_SMEM 149504

__global__ __launch_bounds__(512, 1) void scores_kernel(
    const float* __restrict__ mask,
    const float* __restrict__ structm,
    const float* __restrict__ dist,
    const float* __restrict__ abv)
{
    extern __shared__ __align__(16) char smraw[];
    __half2* Q   = (__half2*)smraw;
    __half2* Kb  = (__half2*)(smraw + 16384);
    __half2* Ka  = (__half2*)(smraw + 32768);
    __half2* E0  = (__half2*)(smraw + 49152);
    __half2* E1  = (__half2*)(smraw + 65536);
    __half*  QB0 = (__half*)(smraw + 81920);    // 128*132 fp16
    __half*  QB1 = (__half*)(smraw + 115712);

    const int bh = blockIdx.x, kt = blockIdx.y, qt = blockIdx.z;
    const int b = bh / HH, h = bh % HH;
    const int m0 = qt*128, n0 = kt*128;
    const int tid = threadIdx.x, lane = tid & 31, wid = tid >> 5;
    const int wm = wid & 3, wn = wid >> 2;
    const int r0 = wm*32 + (lane >> 2);
    const int c0 = wn*32 + (lane & 3)*2;

    const int base = (qt - kt)*128 + 896;
    int nv1 = 1919 - base; if (nv1 > 128) nv1 = 128;

    const float* qwbase = g_qw + ((size_t)bh*LL + m0)*DHD;
    const size_t qwstr = (size_t)BHN*LL*DHD;

    float4 vA[4], vB[4];
    // prologue staging
    ldgT4<4,512>(vA, g_q + (size_t)(bh*LL + m0)*DHD, DHD, tid, 128);
    ldgT4<4,512>(vB, g_k + (size_t)(bh*LL + n0)*DHD, DHD, tid, 128);
    stsAh<4,512>(Q, vA, tid);
    stsAh<4,512>(Ka, vB, tid);
    stsBh<4,512>(Kb, vB, tid);
    ldgT4<4,512>(vA, dist + (size_t)base*DHD, DHD, tid, 128);
    stsBh<4,512>(E0, vA, tid);
    ldgT4<4,512>(vB, dist + (size_t)(base + 128)*DHD, DHD, tid, nv1);
    stsBh<4,512>(E1, vB, tid);
    ldgT4<4,512>(vA, qwbase, DHD, tid, 128);      // qw0 prefetch
    __syncthreads();

    float acc[2][4][4];
    float bacc[2][4][4];
    zero32(acc);

    auto writeQEh = [&](__half* buf) {
        #pragma unroll
        for (int i = 0; i < 2; i++)
            #pragma unroll
            for (int j = 0; j < 4; j++) {
                int rr = r0 + i*16, cc = c0 + j*8;
                *(__half2*)(buf + rr*132 + cc)     = __floats2half2_rn(bacc[i][j][0], bacc[i][j][1]);
                *(__half2*)(buf + (rr+8)*132 + cc) = __floats2half2_rn(bacc[i][j][2], bacc[i][j][3]);
            }
    };
    auto gatherH = [&](const __half* buf, int off, bool useCol) {
        #pragma unroll
        for (int i = 0; i < 2; i++)
            #pragma unroll
            for (int j = 0; j < 4; j++) {
                int rr = r0 + i*16, cc = c0 + j*8;
                #pragma unroll
                for (int c2 = 0; c2 < 4; c2++) {
                    int R = rr + (c2 >> 1)*8;
                    int C = cc + (c2 & 1);
                    int J = R - C + off;
                    if ((unsigned)J < 128u) {
                        int rowi = useCol ? C : R;
                        acc[i][j][c2] += __half2float(buf[rowi*132 + J]);
                    }
                }
            }
    };

    // S1: KE0 -> QB0
    zero32(bacc); gemm32h(Ka, E0, wm, wn, lane, bacc);
    writeQEh(QB0);
    __syncthreads();

    // S2: KE1 -> QB1; gather KE0
    zero32(bacc); gemm32h(Ka, E1, wm, wn, lane, bacc);
    gatherH(QB0, 127, true);
    writeQEh(QB1);
    __syncthreads();

    // S3: QE0 -> QB0; gather KE1; stage qw0->Ka; ldg qw1
    zero32(bacc); gemm32h(Q, E0, wm, wn, lane, bacc);
    gatherH(QB1, -1, true);
    writeQEh(QB0);
    stsAh<4,512>(Ka, vA, tid);
    ldgT4<4,512>(vA, qwbase + qwstr, DHD, tid, 128);
    __syncthreads();

    // S4: QE1 -> QB1; gather QE0; stage qw1->E0; ldg qw2
    zero32(bacc); gemm32h(Q, E1, wm, wn, lane, bacc);
    gatherH(QB0, 127, false);
    writeQEh(QB1);
    stsAh<4,512>(E0, vA, tid);
    ldgT4<4,512>(vA, qwbase + 2*qwstr, DHD, tid, 128);
    __syncthreads();

    // S5: QK; gather QE1; scale+mask; stage qw2->E1; ldg qw3
    float2 mk[4];
    {
        const float* mrow = mask + b*LL + n0;
        #pragma unroll
        for (int j = 0; j < 4; j++) mk[j] = *(const float2*)(mrow + c0 + j*8);
    }
    zero32(bacc); gemm32h(Q, Kb, wm, wn, lane, bacc);
    gatherH(QB1, -1, false);
    #pragma unroll
    for (int j = 0; j < 4; j++)
        #pragma unroll
        for (int i = 0; i < 2; i++) {
            acc[i][j][0] = (acc[i][j][0] + bacc[i][j][0])*0.125f + mk[j].x;
            acc[i][j][1] = (acc[i][j][1] + bacc[i][j][1])*0.125f + mk[j].y;
            acc[i][j][2] = (acc[i][j][2] + bacc[i][j][2])*0.125f + mk[j].x;
            acc[i][j][3] = (acc[i][j][3] + bacc[i][j][3])*0.125f + mk[j].y;
        }
    stsAh<4,512>(E1, vA, tid);
    ldgT4<4,512>(vA, qwbase + 3*qwstr, DHD, tid, 128);
    __syncthreads();

    // bilinear passes: qw0=Ka, qw1=E0, qw2=E1, qw3=Q, qw4=Ka(again)
    float2 sv[8];
    float  ab;
    auto structPre = [&](int i5) {
        ab = __ldg(&abv[i5*HH + h]);
        const float* stb = structm + (((size_t)(i5*BB + b)*LL + m0)*LL) + n0;
        #pragma unroll
        for (int j = 0; j < 4; j++) {
            sv[j*2+0] = *(const float2*)(stb + (size_t)r0*LL + c0 + j*8);
            sv[j*2+1] = *(const float2*)(stb + (size_t)(r0+8)*LL + c0 + j*8);
        }
    };
    auto structEpi = [&](int i5) {
        #pragma unroll
        for (int j = 0; j < 4; j++) {
            acc[0][j][0] += (bacc[0][j][0] + ab)*sv[j*2+0].x;
            acc[0][j][1] += (bacc[0][j][1] + ab)*sv[j*2+0].y;
            acc[0][j][2] += (bacc[0][j][2] + ab)*sv[j*2+1].x;
            acc[0][j][3] += (bacc[0][j][3] + ab)*sv[j*2+1].y;
        }
        const float* stb = structm + (((size_t)(i5*BB + b)*LL + m0)*LL) + n0;
        #pragma unroll
        for (int j = 0; j < 4; j++) {
            float2 s0 = *(const float2*)(stb + (size_t)(r0+16)*LL + c0 + j*8);
            float2 s1 = *(const float2*)(stb + (size_t)(r0+24)*LL + c0 + j*8);
            acc[1][j][0] += (bacc[1][j][0] + ab)*s0.x;
            acc[1][j][1] += (bacc[1][j][1] + ab)*s0.y;
            acc[1][j][2] += (bacc[1][j][2] + ab)*s1.x;
            acc[1][j][3] += (bacc[1][j][3] + ab)*s1.y;
        }
    };

    // B1: bilinear0 (Ka=qw0); stage qw3->Q; ldg qw4
    structPre(0);
    zero32(bacc); gemm32h(Ka, Kb, wm, wn, lane, bacc);
    structEpi(0);
    stsAh<4,512>(Q, vA, tid);
    ldgT4<4,512>(vA, qwbase + 4*qwstr, DHD, tid, 128);
    __syncthreads();

    // B2: bilinear1 (E0=qw1); stage qw4->Ka
    structPre(1);
    zero32(bacc); gemm32h(E0, Kb, wm, wn, lane, bacc);
    structEpi(1);
    stsAh<4,512>(Ka, vA, tid);
    __syncthreads();

    // B3: bilinear2 (E1=qw2)
    structPre(2);
    zero32(bacc); gemm32h(E1, Kb, wm, wn, lane, bacc);
    structEpi(2);

    // B4: bilinear3 (Q=qw3)  [Q staged B1, synced B1]
    structPre(3);
    zero32(bacc); gemm32h(Q, Kb, wm, wn, lane, bacc);
    structEpi(3);

    // B5: bilinear4 (Ka=qw4) [Ka staged B2, synced B2]
    structPre(4);
    zero32(bacc); gemm32h(Ka, Kb, wm, wn, lane, bacc);
    structEpi(4);

    // store scores
    float* sp = g_s + ((size_t)bh*LL + m0)*LL + n0;
    #pragma unroll
    for (int i = 0; i < 2; i++)
        #pragma unroll
        for (int j = 0; j < 4; j++) {
            int rr = r0 + i*16, cc = c0 + j*8;
            *(float2*)(sp + (size_t)rr*LL + cc)     = make_float2(acc[i][j][0], acc[i][j][1]);
            *(float2*)(sp + (size_t)(rr+8)*LL + cc) = make_float2(acc[i][j][2], acc[i][j][3]);
        }
}

// ============================================================
// K3: row stats (max + 1/sum(exp)) — replaces softmax
// ============================================================
__global__ __launch_bounds__(256) void rowstat_kernel()
{
    const int warp = threadIdx.x >> 5, lane = threadIdx.x & 31;
    const size_t row = (size_t)blockIdx.x * 8 + warp;
    const float* rp = g_s + row * LL;

    float4 v[8];
    float mx = -1e30f;
    #pragma unroll
    for (int k2 = 0; k2 < 8; k2++) {
        v[k2] = *(const float4*)&rp[(lane + k2*32)*4];
        mx = fmaxf(mx, fmaxf(fmaxf(v[k2].x, v[k2].y), fmaxf(v[k2].z, v[k2].w)));
    }
    #pragma unroll
    for (int o = 16; o > 0; o >>= 1) mx = fmaxf(mx, __shfl_xor_sync(0xffffffffu, mx, o));

    float s = 0.f;
    #pragma unroll
    for (int k2 = 0; k2 < 8; k2++) {
        s += __expf(v[k2].x - mx) + __expf(v[k2].y - mx)
           + __expf(v[k2].z - mx) + __expf(v[k2].w - mx);
    }
    #pragma unroll
    for (int o = 16; o > 0; o >>= 1) s += __shfl_xor_sync(0xffffffffu, s, o);

    if (lane == 0) {
        g_mx[row]  = mx;
        g_inv[row] = 1.f / s;
    }
}

// ============================================================
// K4: ctx = softmax(scores) @ v, fused exp (fp16 mma, 256 thr)
// smem: Af 16K + Bf 8K + stats 1K = 25600
// ============================================================
__global__ __launch_bounds__(256) void pv_kernel(float* __restrict__ out)
{
    extern __shared__ __align__(16) char smraw[];
    __half2* Af = (__half2*)smraw;
    __half2* Bf = (__half2*)(smraw + 16384);
    float* sm_m   = (float*)(smraw + 24576);
    float* sm_inv = (float*)(smraw + 25088);

    const int bh = blockIdx.y;
    const int b = bh / HH, h = bh % HH;
    const int m0 = blockIdx.x * 128;
    const int tid = threadIdx.x, lane = tid & 31, wid = tid >> 5;

    if (tid < 128) {
        sm_m[tid]   = g_mx [bh*LL + m0 + tid];
        sm_inv[tid] = g_inv[bh*LL + m0 + tid];
    }
    __syncthreads();

    const float* pb = g_s + (size_t)bh*LL*LL + (size_t)m0*LL;
    const float* vb = g_v + (size_t)bh*LL*DHD;

    float acc[8][4];
    #pragma unroll
    for (int j = 0; j < 8; j++)
        #pragma unroll
        for (int c = 0; c < 4; c++) acc[j][c] = 0.f;

    for (int kc0 = 0; kc0 < LL; kc0 += 64) {
        stageAhExp(Af, pb + kc0, LL, tid, sm_m);
        stageBTh<64>(Bf, vb + (size_t)kc0*DHD, DHD, tid);
        __syncthreads();
        gemm64n64h(Af, Bf, wid, lane, acc);
        __syncthreads();
    }

    const int r0 = wid*16 + (lane >> 2);
    const int c0 = (lane & 3)*2;
    const float inv0 = sm_inv[r0];
    const float inv1 = sm_inv[r0 + 8];
    #pragma unroll
    for (int j = 0; j < 8; j++) {
        int cc = c0 + j*8;
        int l0 = m0 + r0;
        *(float2*)&out[((size_t)b*LL + l0)*DD + h*DHD + cc] =
            make_float2(acc[j][0]*inv0, acc[j][1]*inv0);
        *(float2*)&out[((size_t)b*LL + l0 + 8)*DD + h*DHD + cc] =
            make_float2(acc[j][2]*inv1, acc[j][3]*inv1);
    }
}

// ============================================================
extern "C" void kernel_launch(void* const* d_in, const int* in_sizes, int n_in,
                              void* d_out, int out_size)
{
    const float* hidden  = (const float*)d_in[0];
    const float* mask    = (const float*)d_in[1];
    const float* structm = (const float*)d_in[2];
    const float* Wq      = (const float*)d_in[3];
    const float* bq      = (const float*)d_in[4];
    const float* Wk      = (const float*)d_in[5];
    const float* bk      = (const float*)d_in[6];
    const float* Wv      = (const float*)d_in[7];
    const float* bv      = (const float*)d_in[8];
    const float* dist    = (const float*)d_in[9];
    const float* ssw     = (const float*)d_in[10];
    const float* abv     = (const float*)d_in[11];
    float* out = (float*)d_out;

    cudaFuncSetAttribute(qkv_kernel,    cudaFuncAttributeMaxDynamicSharedMemorySize, 32768);
    cudaFuncSetAttribute(qw_kernel,     cudaFuncAttributeMaxDynamicSharedMemorySize, 24576);
    cudaFuncSetAttribute(pv_kernel,     cudaFuncAttributeMaxDynamicSharedMemorySize, 25600);
    cudaFuncSetAttribute(scores_kernel, cudaFuncAttributeMaxDynamicSharedMemorySize, SC_SMEM);

    qkv_kernel    <<<dim3(6,16,3),  256, 32768>>>(hidden, Wq,bq, Wk,bk, Wv,bv);
    qw_kernel     <<<dim3(8,24,5),  256, 24576>>>(ssw);
    scores_kernel <<<dim3(24,8,8),  512, SC_SMEM>>>(mask, structm, dist, abv);
    rowstat_kernel<<<3072,          256>>>();
    pv_kernel     <<<dim3(8,24),    256, 25600>>>(out);
}